// round 1
// baseline (speedup 1.0000x reference)
#include <cuda_runtime.h>
#include <cuda_bf16.h>
#include <math.h>

#define Bb  2
#define NN  8192
#define CA  128
#define CS  384
#define CZ  16
#define HH  4
#define DD  32
#define NQ  32
#define NK  128
#define NB  3
#define WW  256
#define HID 256
#define TT  (Bb*NN)          /* 16384 tokens */
#define ROWS 2097152         /* B*W*NQ*NK */

// ---------------- scratch (device globals; no allocation allowed) ----------------
__device__ float g_sln [(size_t)TT*CS];
__device__ float g_gates[NB*6][(size_t)TT*CA];   // per blk: 0=adaln_sig 1=adaln_shift 2=sgate 3=t_sig 4=t_shift 5=t_sgate
__device__ float g_biasbuf[(size_t)NB*HH*ROWS];  // [blk][h][row]
__device__ float g_aln[(size_t)TT*CA];
__device__ float g_tln[(size_t)TT*CA];
__device__ float g_qh [(size_t)TT*CA];
__device__ float g_kh [(size_t)TT*CA];
__device__ float g_vh [(size_t)TT*CA];
__device__ float g_gh [(size_t)TT*CA];
__device__ float g_att[(size_t)TT*CA];
__device__ float g_ao [(size_t)TT*CA];
__device__ float g_ha [(size_t)TT*HID];
__device__ float g_hb [(size_t)TT*HID];
__device__ float g_a  [(size_t)TT*CA];

__device__ __forceinline__ float sigm(float x){ return 1.f/(1.f+__expf(-x)); }

// reduce (sum, sumsq) across a 128-thread block
__device__ __forceinline__ void blockReduce2_128(float& s, float& q){
    __shared__ float sb[8];
    #pragma unroll
    for (int o=16;o;o>>=1){
        s += __shfl_xor_sync(0xffffffffu, s, o);
        q += __shfl_xor_sync(0xffffffffu, q, o);
    }
    int wid = threadIdx.x>>5;
    if ((threadIdx.x&31)==0){ sb[wid*2]=s; sb[wid*2+1]=q; }
    __syncthreads();
    s = sb[0]+sb[2]+sb[4]+sb[6];
    q = sb[1]+sb[3]+sb[5]+sb[7];
}

// ---------------- K1: layernorm of s (once) ----------------
__global__ void sln_kernel(const float* __restrict__ s){
    int t = blockIdx.x, tid = threadIdx.x;
    const float* row = s + (size_t)t*CS;
    float v0=row[tid], v1=row[tid+128], v2=row[tid+256];
    float su=v0+v1+v2, sq=v0*v0+v1*v1+v2*v2;
    blockReduce2_128(su,sq);
    float mean = su*(1.f/CS);
    float var  = sq*(1.f/CS) - mean*mean;
    float inv  = rsqrtf(var + 1e-5f);
    float* o = g_sln + (size_t)t*CS;
    o[tid]=(v0-mean)*inv; o[tid+128]=(v1-mean)*inv; o[tid+256]=(v2-mean)*inv;
}

// ---------------- K3: pair bias for all 3 blocks (once; reads p a single time) ----------------
__global__ void bias_kernel(const float* __restrict__ p, const float* __restrict__ lnz_w,
                            const float* __restrict__ lnz_b, const float* __restrict__ wb){
    __shared__ float s_w[NB*CZ], s_b[NB*CZ], s_wb[NB*CZ*HH];
    int tid = threadIdx.x;
    if (tid < NB*CZ){ s_w[tid]=lnz_w[tid]; s_b[tid]=lnz_b[tid]; }
    if (tid < NB*CZ*HH) s_wb[tid]=wb[tid];
    __syncthreads();
    size_t r = (size_t)blockIdx.x*blockDim.x + tid;
    if (r >= (size_t)ROWS) return;
    const float4* p4 = (const float4*)(p + r*CZ);
    float z[16];
    float4 q0=p4[0], q1=p4[1], q2=p4[2], q3=p4[3];
    z[0]=q0.x; z[1]=q0.y; z[2]=q0.z; z[3]=q0.w;
    z[4]=q1.x; z[5]=q1.y; z[6]=q1.z; z[7]=q1.w;
    z[8]=q2.x; z[9]=q2.y; z[10]=q2.z; z[11]=q2.w;
    z[12]=q3.x; z[13]=q3.y; z[14]=q3.z; z[15]=q3.w;
    float su=0, sq=0;
    #pragma unroll
    for (int c=0;c<16;c++){ su+=z[c]; sq+=z[c]*z[c]; }
    float mean=su*(1.f/16.f), var=sq*(1.f/16.f)-mean*mean;
    float inv=rsqrtf(var+1e-5f);
    #pragma unroll
    for (int c=0;c<16;c++) z[c]=(z[c]-mean)*inv;
    #pragma unroll
    for (int i=0;i<NB;i++){
        float o0=0,o1=0,o2=0,o3=0;
        #pragma unroll
        for (int c=0;c<16;c++){
            float zz = z[c]*s_w[i*16+c] + s_b[i*16+c];
            const float* w4 = &s_wb[(i*16+c)*4];
            o0 += zz*w4[0]; o1 += zz*w4[1]; o2 += zz*w4[2]; o3 += zz*w4[3];
        }
        size_t base = ((size_t)i*HH)*ROWS + r;
        g_biasbuf[base]        = o0;
        g_biasbuf[base+ROWS]   = o1;
        g_biasbuf[base+2*(size_t)ROWS] = o2;
        g_biasbuf[base+3*(size_t)ROWS] = o3;
    }
}

// ---------------- K4: LN(a) + both modulations (per block) ----------------
__global__ void lnmod_kernel(const float* __restrict__ a, int blk){
    int t = blockIdx.x, c = threadIdx.x;
    float x = a[(size_t)t*CA + c];
    float su=x, sq=x*x;
    blockReduce2_128(su,sq);
    float mean=su*(1.f/CA), var=sq*(1.f/CA)-mean*mean;
    float xn=(x-mean)*rsqrtf(var+1e-5f);
    size_t o=(size_t)t*CA+c;
    g_aln[o] = g_gates[blk*6+0][o]*xn + g_gates[blk*6+1][o];
    g_tln[o] = g_gates[blk*6+3][o]*xn + g_gates[blk*6+4][o];
}

// ---------------- generic tiled GEMM: C[M,N] = A[M,K] @ B[K,N] + epilogue ----------------
// BM=64, BN=64, BK=16, 256 threads, 4x4 per thread.
// A2 != null: A_eff = silu(A)*A2 (GLU input fusion).
// epilogue: +bias[n]; sigmoid for n>=sigStart; *= mulp[m,n]; += addp[m,n]
__global__ void gemm_kernel(const float* __restrict__ A, const float* __restrict__ A2,
                            const float* __restrict__ Bm, const float* __restrict__ bias,
                            const float* __restrict__ mulp, const float* __restrict__ addp,
                            float* __restrict__ C, int M, int N, int K, int sigStart){
    __shared__ float As[16][64];
    __shared__ float Bs[16][64];
    int m0 = blockIdx.x*64, n0 = blockIdx.y*64;
    int tid = threadIdx.x;
    int ar = tid>>2, aq = tid&3;      // A tile load: row 0..63, float4 group 0..3
    int br = tid>>4, bq = tid&15;     // B tile load: row 0..15, float4 group 0..15
    int tr = tid>>4, tc = tid&15;     // compute: 4x4 micro-tile
    float acc[4][4] = {};
    const float* Aptr  = A  + (size_t)(m0+ar)*K + aq*4;
    const float* A2ptr = A2 ? A2 + (size_t)(m0+ar)*K + aq*4 : (const float*)0;
    const float* Bptr  = Bm + (size_t)br*N + n0 + bq*4;
    for (int k0=0; k0<K; k0+=16){
        float4 av = *(const float4*)(Aptr + k0);
        if (A2){
            float4 hv = *(const float4*)(A2ptr + k0);
            av.x = av.x*sigm(av.x)*hv.x;
            av.y = av.y*sigm(av.y)*hv.y;
            av.z = av.z*sigm(av.z)*hv.z;
            av.w = av.w*sigm(av.w)*hv.w;
        }
        As[aq*4+0][ar]=av.x; As[aq*4+1][ar]=av.y; As[aq*4+2][ar]=av.z; As[aq*4+3][ar]=av.w;
        *(float4*)&Bs[br][bq*4] = *(const float4*)(Bptr + (size_t)k0*N);
        __syncthreads();
        #pragma unroll
        for (int k=0;k<16;k++){
            float4 a4 = *(const float4*)&As[k][tr*4];
            float4 b4 = *(const float4*)&Bs[k][tc*4];
            acc[0][0]+=a4.x*b4.x; acc[0][1]+=a4.x*b4.y; acc[0][2]+=a4.x*b4.z; acc[0][3]+=a4.x*b4.w;
            acc[1][0]+=a4.y*b4.x; acc[1][1]+=a4.y*b4.y; acc[1][2]+=a4.y*b4.z; acc[1][3]+=a4.y*b4.w;
            acc[2][0]+=a4.z*b4.x; acc[2][1]+=a4.z*b4.y; acc[2][2]+=a4.z*b4.z; acc[2][3]+=a4.z*b4.w;
            acc[3][0]+=a4.w*b4.x; acc[3][1]+=a4.w*b4.y; acc[3][2]+=a4.w*b4.z; acc[3][3]+=a4.w*b4.w;
        }
        __syncthreads();
    }
    #pragma unroll
    for (int j=0;j<4;j++){
        #pragma unroll
        for (int l=0;l<4;l++){
            int n = n0 + tc*4 + l;
            size_t m = (size_t)m0 + tr*4 + j;
            float v = acc[j][l];
            if (bias) v += bias[n];
            if (n >= sigStart) v = sigm(v);
            size_t off = m*(size_t)N + n;
            if (mulp) v *= mulp[off];
            if (addp) v += addp[off];
            C[off] = v;
        }
    }
}

// ---------------- K6: windowed attention, one CTA per (b, w, h) ----------------
__global__ void attn_kernel(int blk){
    __shared__ float qs[NQ*DD];       // 32x32
    __shared__ float kv[NK*33];       // 128x32 padded (K tile, later reused as V tile)
    __shared__ float lb[NQ*129];      // bias -> logits -> attn, padded rows
    int w = blockIdx.x, h = blockIdx.y, b = blockIdx.z;
    int tid = threadIdx.x;            // 256
    size_t tokbase = (size_t)b*NN + (size_t)w*NQ;
    int kstart = w*NQ - 48;           // (NK-NQ)/2 = 48
    // load Q
    for (int i=tid; i<NQ*DD; i+=256){
        int r=i>>5, c=i&31;
        qs[i] = g_qh[(tokbase+r)*CA + h*DD + c];
    }
    // load K (clamped; masked later)
    for (int i=tid; i<NK*DD; i+=256){
        int r=i>>5, c=i&31;
        int src = kstart + r; src = min(max(src,0), NN-1);
        kv[r*33+c] = g_kh[((size_t)b*NN + src)*CA + h*DD + c];
    }
    // load bias plane (coalesced: stored [blk][h][row])
    const float* plane = g_biasbuf + ((size_t)blk*HH + h)*(size_t)ROWS;
    size_t rb = (((size_t)b*WW + w)*NQ)*NK;
    for (int i=tid; i<NQ*NK; i+=256){
        int q=i>>7, k=i&127;
        lb[q*129+k] = plane[rb + i];
    }
    __syncthreads();
    // logits: 4q x 4k tile per thread (k strided by 32 for conflict-free smem)
    {
        int qt = tid>>5, kt = tid&31;
        float acc[4][4] = {};
        #pragma unroll
        for (int d=0; d<DD; d++){
            float qa[4], kb[4];
            #pragma unroll
            for (int j=0;j<4;j++) qa[j] = qs[(qt*4+j)*DD + d];
            #pragma unroll
            for (int l=0;l<4;l++) kb[l] = kv[(kt+32*l)*33 + d];
            #pragma unroll
            for (int j=0;j<4;j++)
                #pragma unroll
                for (int l=0;l<4;l++) acc[j][l] += qa[j]*kb[l];
        }
        const float isd = 0.17677669529663687f;  // 1/sqrt(32)
        #pragma unroll
        for (int j=0;j<4;j++){
            #pragma unroll
            for (int l=0;l<4;l++){
                int q = qt*4+j, k = kt+32*l;
                int src = kstart + k;
                float v = (src>=0 && src<NN) ? acc[j][l]*isd + lb[q*129+k] : -1e9f;
                lb[q*129+k] = v;
            }
        }
    }
    __syncthreads();
    // load V into kv (K tile no longer needed)
    for (int i=tid; i<NK*DD; i+=256){
        int r=i>>5, c=i&31;
        int src = kstart + r; src = min(max(src,0), NN-1);
        kv[r*33+c] = g_vh[((size_t)b*NN + src)*CA + h*DD + c];
    }
    // softmax: 8 warps x 4 rows (lb only; overlaps with V load)
    {
        int wid = tid>>5, lane = tid&31;
        for (int rq=0; rq<4; rq++){
            int q = wid*4 + rq;
            float m = -1e30f;
            #pragma unroll
            for (int k=lane; k<NK; k+=32) m = fmaxf(m, lb[q*129+k]);
            #pragma unroll
            for (int o=16;o;o>>=1) m = fmaxf(m, __shfl_xor_sync(0xffffffffu, m, o));
            float ssum = 0.f;
            #pragma unroll
            for (int k=lane; k<NK; k+=32){
                float e = __expf(lb[q*129+k] - m);
                lb[q*129+k] = e; ssum += e;
            }
            #pragma unroll
            for (int o=16;o;o>>=1) ssum += __shfl_xor_sync(0xffffffffu, ssum, o);
            float invs = 1.f/ssum;
            #pragma unroll
            for (int k=lane; k<NK; k+=32) lb[q*129+k] *= invs;
        }
    }
    __syncthreads();
    // AV: 2q x 2d per thread, then gate-multiply and store
    {
        int qp = tid>>4, dp = tid&15;
        float av[2][2] = {};
        #pragma unroll 4
        for (int k=0;k<NK;k++){
            float p0 = lb[(qp*2  )*129 + k];
            float p1 = lb[(qp*2+1)*129 + k];
            float v0 = kv[k*33 + dp];
            float v1 = kv[k*33 + dp + 16];
            av[0][0]+=p0*v0; av[0][1]+=p0*v1; av[1][0]+=p1*v0; av[1][1]+=p1*v1;
        }
        #pragma unroll
        for (int a2=0;a2<2;a2++){
            #pragma unroll
            for (int b2=0;b2<2;b2++){
                int q = qp*2+a2, d = dp+16*b2;
                size_t off = (tokbase+q)*CA + h*DD + d;
                g_att[off] = g_gh[off]*av[a2][b2];
            }
        }
    }
}

// ---------------- host launcher ----------------
extern "C" void kernel_launch(void* const* d_in, const int* in_sizes, int n_in,
                              void* d_out, int out_size){
    const float* q_in   = (const float*)d_in[0];
    const float* s_in   = (const float*)d_in[1];
    const float* p_in   = (const float*)d_in[2];
    const float* adaln_scale_w = (const float*)d_in[3];
    const float* adaln_scale_b = (const float*)d_in[4];
    const float* adaln_shift_w = (const float*)d_in[5];
    const float* wq = (const float*)d_in[6];
    const float* bq = (const float*)d_in[7];
    const float* wk = (const float*)d_in[8];
    const float* wv = (const float*)d_in[9];
    const float* lnz_w = (const float*)d_in[10];
    const float* lnz_b = (const float*)d_in[11];
    const float* wb_pair = (const float*)d_in[12];
    const float* wg = (const float*)d_in[13];
    const float* wo = (const float*)d_in[14];
    const float* sgate_w = (const float*)d_in[15];
    const float* sgate_b = (const float*)d_in[16];
    const float* t_scale_w = (const float*)d_in[17];
    const float* t_scale_b = (const float*)d_in[18];
    const float* t_shift_w = (const float*)d_in[19];
    const float* t_wa = (const float*)d_in[20];
    const float* t_wb = (const float*)d_in[21];
    const float* t_wo = (const float*)d_in[22];
    const float* t_sgate_w = (const float*)d_in[23];
    const float* t_sgate_b = (const float*)d_in[24];
    float* out = (float*)d_out;

    float *p_sln, *p_gates, *p_aln, *p_tln, *p_q, *p_k, *p_v, *p_g, *p_att, *p_ao, *p_ha, *p_hb, *p_a;
    cudaGetSymbolAddress((void**)&p_sln,  g_sln);
    cudaGetSymbolAddress((void**)&p_gates,g_gates);
    cudaGetSymbolAddress((void**)&p_aln,  g_aln);
    cudaGetSymbolAddress((void**)&p_tln,  g_tln);
    cudaGetSymbolAddress((void**)&p_q,    g_qh);
    cudaGetSymbolAddress((void**)&p_k,    g_kh);
    cudaGetSymbolAddress((void**)&p_v,    g_vh);
    cudaGetSymbolAddress((void**)&p_g,    g_gh);
    cudaGetSymbolAddress((void**)&p_att,  g_att);
    cudaGetSymbolAddress((void**)&p_ao,   g_ao);
    cudaGetSymbolAddress((void**)&p_ha,   g_ha);
    cudaGetSymbolAddress((void**)&p_hb,   g_hb);
    cudaGetSymbolAddress((void**)&p_a,    g_a);

    const int NOSIG = 1<<30;
    #define GATE(i,g) (p_gates + ((size_t)((i)*6+(g)))*((size_t)TT*CA))
    #define GEMM(A,A2,Bm,bias,mul,add,C,M,N,K,sig) \
        gemm_kernel<<<dim3((M)/64,(N)/64),256>>>((A),(A2),(Bm),(bias),(mul),(add),(C),(M),(N),(K),(sig))

    // stage 0: invariants
    sln_kernel<<<TT,128>>>(s_in);
    bias_kernel<<<ROWS/256,256>>>(p_in, lnz_w, lnz_b, wb_pair);
    for (int i=0;i<NB;i++){
        GEMM(p_sln,(const float*)0, adaln_scale_w+(size_t)i*CS*CA, adaln_scale_b+i*CA, (const float*)0,(const float*)0, GATE(i,0), TT,CA,CS, 0);
        GEMM(p_sln,(const float*)0, adaln_shift_w+(size_t)i*CS*CA, (const float*)0,    (const float*)0,(const float*)0, GATE(i,1), TT,CA,CS, NOSIG);
        GEMM(p_sln,(const float*)0, sgate_w      +(size_t)i*CS*CA, sgate_b+i*CA,       (const float*)0,(const float*)0, GATE(i,2), TT,CA,CS, 0);
        GEMM(p_sln,(const float*)0, t_scale_w    +(size_t)i*CS*CA, t_scale_b+i*CA,     (const float*)0,(const float*)0, GATE(i,3), TT,CA,CS, 0);
        GEMM(p_sln,(const float*)0, t_shift_w    +(size_t)i*CS*CA, (const float*)0,    (const float*)0,(const float*)0, GATE(i,4), TT,CA,CS, NOSIG);
        GEMM(p_sln,(const float*)0, t_sgate_w    +(size_t)i*CS*CA, t_sgate_b+i*CA,     (const float*)0,(const float*)0, GATE(i,5), TT,CA,CS, 0);
    }

    // stage 1: the 3 transformer blocks
    const float* acur = q_in;
    for (int i=0;i<NB;i++){
        lnmod_kernel<<<TT,128>>>(acur, i);
        GEMM(p_aln,(const float*)0, wq+(size_t)i*CA*CA, bq+i*CA,        (const float*)0,(const float*)0, p_q, TT,CA,CA, NOSIG);
        GEMM(p_aln,(const float*)0, wk+(size_t)i*CA*CA, (const float*)0,(const float*)0,(const float*)0, p_k, TT,CA,CA, NOSIG);
        GEMM(p_aln,(const float*)0, wv+(size_t)i*CA*CA, (const float*)0,(const float*)0,(const float*)0, p_v, TT,CA,CA, NOSIG);
        GEMM(p_aln,(const float*)0, wg+(size_t)i*CA*CA, (const float*)0,(const float*)0,(const float*)0, p_g, TT,CA,CA, 0);
        attn_kernel<<<dim3(WW,HH,Bb),256>>>(i);
        GEMM(p_att,(const float*)0, wo+(size_t)i*CA*CA, (const float*)0, GATE(i,2), (const float*)0, p_ao, TT,CA,CA, NOSIG);
        GEMM(p_tln,(const float*)0, t_wa+(size_t)i*CA*HID, (const float*)0,(const float*)0,(const float*)0, p_ha, TT,HID,CA, NOSIG);
        GEMM(p_tln,(const float*)0, t_wb+(size_t)i*CA*HID, (const float*)0,(const float*)0,(const float*)0, p_hb, TT,HID,CA, NOSIG);
        float* dst = (i==NB-1) ? out : p_a;
        GEMM(p_ha, p_hb, t_wo+(size_t)i*HID*CA, (const float*)0, GATE(i,5), p_ao, dst, TT,CA,HID, NOSIG);
        acur = p_a;
    }
    #undef GEMM
    #undef GATE
    (void)in_sizes; (void)n_in; (void)out_size;
}